// round 8
// baseline (speedup 1.0000x reference)
#include <cuda_runtime.h>
#include <cuda_bf16.h>

#define THREADS 512
#define VT      128000
#define VS      32000
#define KSEL    256
#define MAXB    2048

// monotone float->uint key
__device__ __forceinline__ unsigned f2k(float x) {
    unsigned u = __float_as_uint(x);
    return (u & 0x80000000u) ? ~u : (u | 0x80000000u);
}
__device__ __forceinline__ float k2f(unsigned k) {
    unsigned u = (k & 0x80000000u) ? (k & 0x7fffffffu) : ~k;
    return __uint_as_float(u);
}

__global__ void __launch_bounds__(THREADS, 4)
vocab_project_kernel(const float* __restrict__ logits,
                     const void* __restrict__ mapping,
                     float* __restrict__ out) {
    __shared__ unsigned h256[256];
    __shared__ unsigned tKey[2][MAXB], tIdx[2][MAXB];
    __shared__ float    fred[THREADS];
    __shared__ float    fred2[THREADS];
    __shared__ unsigned selKey[KSEL], selIdx[KSEL];
    __shared__ int      s_bin;
    __shared__ unsigned s_above;
    __shared__ int      nCand, selCount, nNext, s_is64;
    __shared__ unsigned s_maxkey, s_minkey;
    __shared__ float    s_mean, s_std, s_denom;

    const int tid = threadIdx.x;
    const int row = blockIdx.x;
    const float* __restrict__ rowf = logits + (size_t)row * VT;
    const float4* __restrict__ rp = (const float4*)rowf;
    float* __restrict__ orow = out + (size_t)row * VS;

    // ---- init + mapping dtype detect ----
    if (tid == 0) {
        const unsigned* m32 = (const unsigned*)mapping;
        int all0 = 1;
        for (int i = 1; i < 64; i += 2)
            if (m32[i] != 0u) { all0 = 0; break; }
        s_is64 = all0;
        s_denom = 0.0f;
        selCount = 0;
    }

    // ---- full pass: collect (key, idx) >= threshold ----
    // Common case: fixed threshold for ~N(0,1) rows; sampled-stats fallback
    // re-tries with an adjusted threshold for arbitrary distributions.
    float thrVal = 2.45f;               // E[count] ~ 915 for standard normal
    float stdGuess = 1.0f;
    bool haveStats = false;
    for (int attempt = 0; attempt < 10; attempt++) {
        if (tid == 0) { nCand = 0; s_maxkey = 0u; s_minkey = 0xFFFFFFFFu; }
        __syncthreads();
        // 16 floats (4 x float4) per iteration, streaming (evict-first) loads
        for (int i = tid; i < VT / 16; i += THREADS) {
            const float4 a = __ldcs(&rp[4 * i + 0]);
            const float4 b = __ldcs(&rp[4 * i + 1]);
            const float4 c = __ldcs(&rp[4 * i + 2]);
            const float4 d = __ldcs(&rp[4 * i + 3]);
            float m0 = fmaxf(fmaxf(a.x, a.y), fmaxf(a.z, a.w));
            float m1 = fmaxf(fmaxf(b.x, b.y), fmaxf(b.z, b.w));
            float m2 = fmaxf(fmaxf(c.x, c.y), fmaxf(c.z, c.w));
            float m3 = fmaxf(fmaxf(d.x, d.y), fmaxf(d.z, d.w));
            if (fmaxf(fmaxf(m0, m1), fmaxf(m2, m3)) >= thrVal) {
                const float v[16] = {a.x,a.y,a.z,a.w, b.x,b.y,b.z,b.w,
                                     c.x,c.y,c.z,c.w, d.x,d.y,d.z,d.w};
#pragma unroll
                for (int j = 0; j < 16; j++) {
                    if (v[j] >= thrVal) {
                        unsigned key = f2k(v[j]);
                        int p = atomicAdd(&nCand, 1);
                        if (p < MAXB) {
                            tKey[0][p] = key;
                            tIdx[0][p] = (unsigned)(i * 16 + j);
                            atomicMax(&s_maxkey, key);
                            atomicMin(&s_minkey, key);
                        }
                    }
                }
            }
        }
        __syncthreads();
        int nc = nCand;
        if (nc >= KSEL && nc <= MAXB) break;
        if (!haveStats) {
            // sampled mean/std (rare path)
            float x = rowf[tid * (VT / THREADS)];
            fred[tid] = x;
            fred2[tid] = x * x;
            __syncthreads();
            for (int s = THREADS / 2; s > 0; s >>= 1) {
                if (tid < s) {
                    fred[tid] += fred[tid + s];
                    fred2[tid] += fred2[tid + s];
                }
                __syncthreads();
            }
            if (tid == 0) {
                float mean = fred[0] * (1.0f / THREADS);
                float var  = fred2[0] * (1.0f / THREADS) - mean * mean;
                s_mean = mean;
                s_std  = sqrtf(fmaxf(var, 1e-12f));
            }
            __syncthreads();
            stdGuess = s_std;
            float cand = s_mean + 2.45f * s_std;
            if (fabsf(cand - thrVal) < 0.05f * s_std)
                cand += (nc < KSEL) ? -0.60f * s_std : 0.35f * s_std;
            thrVal = cand;
            haveStats = true;
        } else {
            if (nc < KSEL) thrVal -= 0.60f * stdGuess + 1e-6f;
            else           thrVal += 0.35f * stdGuess + 1e-6f;
        }
        __syncthreads();
    }

    // ---- zero own output row (streaming stores) ----
    {
        float4 z = make_float4(0.f, 0.f, 0.f, 0.f);
        float4* op = (float4*)orow;
        for (int i = tid; i < VS / 4; i += THREADS) __stcs(&op[i], z);
    }

    // ---- exact top-KSEL: byte-radix select starting at highest differing byte ----
    int cur = 0;
    int curN = nCand < MAXB ? nCand : MAXB;
    int need = KSEL;
    const unsigned keyxor = s_minkey ^ s_maxkey;
    int level_start = (keyxor == 0u) ? -1 : (3 - (__clz(keyxor) >> 3));
    __syncthreads();

    for (int level = level_start; level >= 0 && need > 0; level--) {
        if (curN == need) {
            for (int p = tid; p < curN; p += THREADS) {
                int q = atomicAdd(&selCount, 1);
                selKey[q] = tKey[cur][p]; selIdx[q] = tIdx[cur][p];
            }
            need = 0;
            __syncthreads();
            break;
        }
        if (tid < 256) h256[tid] = 0u;
        __syncthreads();
        const int sh = level * 8;
        for (int p = tid; p < curN; p += THREADS)
            atomicAdd(&h256[(tKey[cur][p] >> sh) & 0xFFu], 1u);
        __syncthreads();
        // single-warp top-down scan over 256 bins: find crossing bin
        if (tid < 32) {
            unsigned local[8];
            unsigned part = 0;
#pragma unroll
            for (int j = 0; j < 8; j++) {
                local[j] = h256[255 - (tid * 8 + j)];
                part += local[j];
            }
            unsigned incl = part;
#pragma unroll
            for (int off = 1; off < 32; off <<= 1) {
                unsigned v = __shfl_up_sync(0xffffffffu, incl, off);
                if (tid >= off) incl += v;
            }
            unsigned before = incl - part;
            if (before < (unsigned)need && incl >= (unsigned)need) {
                unsigned cum = before;
#pragma unroll
                for (int j = 0; j < 8; j++) {
                    unsigned c = local[j];
                    if (cum + c >= (unsigned)need) {
                        s_bin = 255 - (tid * 8 + j);
                        s_above = cum;
                        break;
                    }
                    cum += c;
                }
            }
        }
        if (tid == 0) nNext = 0;
        __syncthreads();
        const int c = s_bin;
        const int G = (int)s_above;
        const int oth = cur ^ 1;
        for (int p = tid; p < curN; p += THREADS) {
            unsigned key = tKey[cur][p];
            int byte = (int)((key >> sh) & 0xFFu);
            if (byte > c) {
                int q = atomicAdd(&selCount, 1);
                selKey[q] = key; selIdx[q] = tIdx[cur][p];
            } else if (byte == c) {
                int q = atomicAdd(&nNext, 1);
                tKey[oth][q] = key; tIdx[oth][q] = tIdx[cur][p];
            }
        }
        __syncthreads();
        need -= G;
        curN = nNext;
        cur = oth;
        __syncthreads();
    }

    // remaining entries have IDENTICAL keys; take `need` smallest indices
    if (need > 0) {
        for (int p = tid; p < curN; p += THREADS) {
            unsigned my = tIdx[cur][p];
            int rank = 0;
            for (int j = 0; j < curN; j++) rank += (tIdx[cur][j] < my);
            if (rank < need) {
                int q = atomicAdd(&selCount, 1);
                selKey[q] = tKey[cur][p]; selIdx[q] = my;
            }
        }
        __syncthreads();
    }

    // ---- max logit = global max key (tracked during collection) ----
    const float vmax = k2f(s_maxkey);

    // ---- weights + denominator (warp shfl reduce + shared atomics) ----
    float w = 0.0f;
    if (tid < KSEL) {
        w = exp2f((k2f(selKey[tid]) - vmax) * 0.36067376022224085f); // 1/(4 ln2)
        float ws = w;
#pragma unroll
        for (int off = 16; off > 0; off >>= 1)
            ws += __shfl_xor_sync(0xffffffffu, ws, off);
        if ((tid & 31) == 0) atomicAdd(&s_denom, ws);
    }
    __syncthreads();
    const float inv = 1.0f / s_denom;

    // ---- scatter: gather sid, atomic add into zeroed row (handles dups) ----
    if (tid < KSEL) {
        unsigned idx = selIdx[tid];
        int sid;
        if (s_is64) sid = (int)((const long long*)mapping)[idx];
        else        sid = ((const int*)mapping)[idx];
        atomicAdd(&orow[sid], w * inv);
    }
}

extern "C" void kernel_launch(void* const* d_in, const int* in_sizes, int n_in,
                              void* d_out, int out_size) {
    const float* logits  = (const float*)d_in[0];
    const void*  mapping = d_in[1];
    float* out = (float*)d_out;
    int rows = in_sizes[0] / VT;   // B*T = 2048
    vocab_project_kernel<<<rows, THREADS>>>(logits, mapping, out);
}

// round 9
// speedup vs baseline: 1.4898x; 1.4898x over previous
#include <cuda_runtime.h>
#include <cuda_bf16.h>

#define THREADS 512
#define VT      128000
#define VS      32000
#define KSEL    256
#define MAXB    2048
#define NROWS   2048
#define GRID    608

__device__ int g_row_ctr = 0;
__device__ int g_done_ctr = 0;

// monotone float->uint key
__device__ __forceinline__ unsigned f2k(float x) {
    unsigned u = __float_as_uint(x);
    return (u & 0x80000000u) ? ~u : (u | 0x80000000u);
}
__device__ __forceinline__ float k2f(unsigned k) {
    unsigned u = (k & 0x80000000u) ? (k & 0x7fffffffu) : ~k;
    return __uint_as_float(u);
}

__global__ void __launch_bounds__(THREADS, 4)
vocab_project_kernel(const float* __restrict__ logits,
                     const void* __restrict__ mapping,
                     float* __restrict__ out,
                     int nrows) {
    __shared__ unsigned h256[256];
    __shared__ unsigned tKey[2][MAXB], tIdx[2][MAXB];
    __shared__ float    fred[THREADS];
    __shared__ float    fred2[THREADS];
    __shared__ unsigned selKey[KSEL], selIdx[KSEL];
    __shared__ int      s_bin;
    __shared__ unsigned s_above;
    __shared__ int      nCand, selCount, nNext, s_is64, s_row;
    __shared__ unsigned s_maxkey, s_minkey;
    __shared__ float    s_mean, s_std, s_denom;

    const int tid = threadIdx.x;

    // ---- mapping dtype detect (once per CTA) ----
    if (tid == 0) {
        const unsigned* m32 = (const unsigned*)mapping;
        int all0 = 1;
        for (int i = 1; i < 64; i += 2)
            if (m32[i] != 0u) { all0 = 0; break; }
        s_is64 = all0;
    }

    for (;;) {
        // ---- pull next row (dynamic load balance) ----
        if (tid == 0) {
            s_row = atomicAdd(&g_row_ctr, 1);
            s_denom = 0.0f;
            selCount = 0;
        }
        __syncthreads();
        const int row = s_row;
        if (row >= nrows) break;

        const float* __restrict__ rowf = logits + (size_t)row * VT;
        const float4* __restrict__ rp = (const float4*)rowf;
        float* __restrict__ orow = out + (size_t)row * VS;

        // ---- full pass: collect (key, idx) >= threshold ----
        float thrVal = 2.45f;            // E[count] ~ 915 for standard normal
        float stdGuess = 1.0f;
        bool haveStats = false;
        for (int attempt = 0; attempt < 10; attempt++) {
            if (tid == 0) { nCand = 0; s_maxkey = 0u; s_minkey = 0xFFFFFFFFu; }
            __syncthreads();
            // 16 floats (4 x float4) per iteration
            for (int i = tid; i < VT / 16; i += THREADS) {
                const float4 a = rp[4 * i + 0];
                const float4 b = rp[4 * i + 1];
                const float4 c = rp[4 * i + 2];
                const float4 d = rp[4 * i + 3];
                float m0 = fmaxf(fmaxf(a.x, a.y), fmaxf(a.z, a.w));
                float m1 = fmaxf(fmaxf(b.x, b.y), fmaxf(b.z, b.w));
                float m2 = fmaxf(fmaxf(c.x, c.y), fmaxf(c.z, c.w));
                float m3 = fmaxf(fmaxf(d.x, d.y), fmaxf(d.z, d.w));
                if (fmaxf(fmaxf(m0, m1), fmaxf(m2, m3)) >= thrVal) {
                    const float v[16] = {a.x,a.y,a.z,a.w, b.x,b.y,b.z,b.w,
                                         c.x,c.y,c.z,c.w, d.x,d.y,d.z,d.w};
#pragma unroll
                    for (int j = 0; j < 16; j++) {
                        if (v[j] >= thrVal) {
                            unsigned key = f2k(v[j]);
                            int p = atomicAdd(&nCand, 1);
                            if (p < MAXB) {
                                tKey[0][p] = key;
                                tIdx[0][p] = (unsigned)(i * 16 + j);
                                atomicMax(&s_maxkey, key);
                                atomicMin(&s_minkey, key);
                            }
                        }
                    }
                }
            }
            __syncthreads();
            int nc = nCand;
            if (nc >= KSEL && nc <= MAXB) break;
            if (!haveStats) {
                // sampled mean/std (rare path)
                float x = rowf[tid * (VT / THREADS)];
                fred[tid] = x;
                fred2[tid] = x * x;
                __syncthreads();
                for (int s = THREADS / 2; s > 0; s >>= 1) {
                    if (tid < s) {
                        fred[tid] += fred[tid + s];
                        fred2[tid] += fred2[tid + s];
                    }
                    __syncthreads();
                }
                if (tid == 0) {
                    float mean = fred[0] * (1.0f / THREADS);
                    float var  = fred2[0] * (1.0f / THREADS) - mean * mean;
                    s_mean = mean;
                    s_std  = sqrtf(fmaxf(var, 1e-12f));
                }
                __syncthreads();
                stdGuess = s_std;
                float cand = s_mean + 2.45f * s_std;
                if (fabsf(cand - thrVal) < 0.05f * s_std)
                    cand += (nc < KSEL) ? -0.60f * s_std : 0.35f * s_std;
                thrVal = cand;
                haveStats = true;
            } else {
                if (nc < KSEL) thrVal -= 0.60f * stdGuess + 1e-6f;
                else           thrVal += 0.35f * stdGuess + 1e-6f;
            }
            __syncthreads();
        }

        // ---- zero own output row ----
        {
            float4 z = make_float4(0.f, 0.f, 0.f, 0.f);
            float4* op = (float4*)orow;
            for (int i = tid; i < VS / 4; i += THREADS) op[i] = z;
        }

        // ---- exact top-KSEL: byte-radix select from highest differing byte ----
        int cur = 0;
        int curN = nCand < MAXB ? nCand : MAXB;
        int need = KSEL;
        const unsigned keyxor = s_minkey ^ s_maxkey;
        int level_start = (keyxor == 0u) ? -1 : (3 - (__clz(keyxor) >> 3));
        __syncthreads();

        for (int level = level_start; level >= 0 && need > 0; level--) {
            if (curN == need) {
                for (int p = tid; p < curN; p += THREADS) {
                    int q = atomicAdd(&selCount, 1);
                    selKey[q] = tKey[cur][p]; selIdx[q] = tIdx[cur][p];
                }
                need = 0;
                __syncthreads();
                break;
            }
            if (tid < 256) h256[tid] = 0u;
            __syncthreads();
            const int sh = level * 8;
            for (int p = tid; p < curN; p += THREADS)
                atomicAdd(&h256[(tKey[cur][p] >> sh) & 0xFFu], 1u);
            __syncthreads();
            // single-warp top-down scan over 256 bins: find crossing bin
            if (tid < 32) {
                unsigned local[8];
                unsigned part = 0;
#pragma unroll
                for (int j = 0; j < 8; j++) {
                    local[j] = h256[255 - (tid * 8 + j)];
                    part += local[j];
                }
                unsigned incl = part;
#pragma unroll
                for (int off = 1; off < 32; off <<= 1) {
                    unsigned v = __shfl_up_sync(0xffffffffu, incl, off);
                    if (tid >= off) incl += v;
                }
                unsigned before = incl - part;
                if (before < (unsigned)need && incl >= (unsigned)need) {
                    unsigned cum = before;
#pragma unroll
                    for (int j = 0; j < 8; j++) {
                        unsigned c = local[j];
                        if (cum + c >= (unsigned)need) {
                            s_bin = 255 - (tid * 8 + j);
                            s_above = cum;
                            break;
                        }
                        cum += c;
                    }
                }
            }
            if (tid == 0) nNext = 0;
            __syncthreads();
            const int c = s_bin;
            const int G = (int)s_above;
            const int oth = cur ^ 1;
            for (int p = tid; p < curN; p += THREADS) {
                unsigned key = tKey[cur][p];
                int byte = (int)((key >> sh) & 0xFFu);
                if (byte > c) {
                    int q = atomicAdd(&selCount, 1);
                    selKey[q] = key; selIdx[q] = tIdx[cur][p];
                } else if (byte == c) {
                    int q = atomicAdd(&nNext, 1);
                    tKey[oth][q] = key; tIdx[oth][q] = tIdx[cur][p];
                }
            }
            __syncthreads();
            need -= G;
            curN = nNext;
            cur = oth;
            __syncthreads();
        }

        // remaining entries have IDENTICAL keys; take `need` smallest indices
        if (need > 0) {
            for (int p = tid; p < curN; p += THREADS) {
                unsigned my = tIdx[cur][p];
                int rank = 0;
                for (int j = 0; j < curN; j++) rank += (tIdx[cur][j] < my);
                if (rank < need) {
                    int q = atomicAdd(&selCount, 1);
                    selKey[q] = tKey[cur][p]; selIdx[q] = my;
                }
            }
            __syncthreads();
        }

        // ---- max logit = global max key (tracked during collection) ----
        const float vmax = k2f(s_maxkey);

        // ---- weights + denominator (warp shfl reduce + shared atomics) ----
        float w = 0.0f;
        if (tid < KSEL) {
            w = exp2f((k2f(selKey[tid]) - vmax) * 0.36067376022224085f); // 1/(4 ln2)
            float ws = w;
#pragma unroll
            for (int off = 16; off > 0; off >>= 1)
                ws += __shfl_xor_sync(0xffffffffu, ws, off);
            if ((tid & 31) == 0) atomicAdd(&s_denom, ws);
        }
        __syncthreads();
        const float inv = 1.0f / s_denom;

        // ---- scatter: gather sid, atomic add into zeroed row ----
        if (tid < KSEL) {
            unsigned idx = selIdx[tid];
            int sid;
            if (s_is64) sid = (int)((const long long*)mapping)[idx];
            else        sid = ((const int*)mapping)[idx];
            atomicAdd(&orow[sid], w * inv);
        }
        __syncthreads();   // protect shared state before next row iteration
    }

    // ---- self-reset counters for next (graph-replayed) launch ----
    __syncthreads();
    if (tid == 0) {
        __threadfence();
        int d = atomicAdd(&g_done_ctr, 1);
        if (d == gridDim.x - 1) {
            g_row_ctr = 0;
            g_done_ctr = 0;
            __threadfence();
        }
    }
}

extern "C" void kernel_launch(void* const* d_in, const int* in_sizes, int n_in,
                              void* d_out, int out_size) {
    const float* logits  = (const float*)d_in[0];
    const void*  mapping = d_in[1];
    float* out = (float*)d_out;
    int rows = in_sizes[0] / VT;   // B*T = 2048
    vocab_project_kernel<<<GRID, THREADS>>>(logits, mapping, out, rows);
}